// round 2
// baseline (speedup 1.0000x reference)
#include <cuda_runtime.h>
#include <cuda_bf16.h>
#include <cstdint>

#define N_ROWS   65536
#define K_CENT   512
#define D_DIM    1024
#define TILE_M   128
#define CH_N     256          // centers per chunk
#define NCHUNK   2
#define KSLAB    64
#define NSLABS   (D_DIM / KSLAB)   // 16
#define TAU_F    0.1f
#define EPS_F    1e-8f

// Normalized centers in bf16 (1/||c|| folded in), row-major [K_CENT][D_DIM]
__device__ __align__(16) __nv_bfloat16 g_cbf[K_CENT * D_DIM];
// Per-chunk partial softmax stats
__device__ float g_pm[NCHUNK * N_ROWS];
__device__ float g_ps[NCHUNK * N_ROWS];
__device__ float g_plv[NCHUNK * N_ROWS];

// ---------------- helpers ----------------
__device__ __forceinline__ uint32_t smem_u32(const void* p) {
    uint32_t a;
    asm("{ .reg .u64 t; cvta.to.shared.u64 t, %1; cvt.u32.u64 %0, t; }" : "=r"(a) : "l"(p));
    return a;
}
#define SWZ(o) ((o) ^ ((((uint32_t)(o)) >> 3) & 0x70u))

__device__ __forceinline__ void cp16(uint32_t dst, const void* src) {
    asm volatile("cp.async.cg.shared.global [%0], [%1], 16;"
                 :: "r"(dst), "l"(__cvta_generic_to_global(src)) : "memory");
}
#define CP_COMMIT() asm volatile("cp.async.commit_group;" ::: "memory")
#define CP_WAIT0()  asm volatile("cp.async.wait_group 0;" ::: "memory")

__device__ __forceinline__ void ldsm4(uint32_t* r, uint32_t addr) {
    asm volatile("ldmatrix.sync.aligned.m8n8.x4.shared.b16 {%0,%1,%2,%3}, [%4];"
                 : "=r"(r[0]), "=r"(r[1]), "=r"(r[2]), "=r"(r[3]) : "r"(addr));
}

__device__ __forceinline__ void mma16816(float* d, const uint32_t* a,
                                         uint32_t b0, uint32_t b1) {
    asm volatile(
        "mma.sync.aligned.m16n8k16.row.col.f32.bf16.bf16.f32 "
        "{%0,%1,%2,%3}, {%4,%5,%6,%7}, {%8,%9}, {%0,%1,%2,%3};"
        : "+f"(d[0]), "+f"(d[1]), "+f"(d[2]), "+f"(d[3])
        : "r"(a[0]), "r"(a[1]), "r"(a[2]), "r"(a[3]), "r"(b0), "r"(b1));
}

__device__ __forceinline__ uint32_t pk(float x, float y) {
    __nv_bfloat162 h = __floats2bfloat162_rn(x, y);
    return *reinterpret_cast<uint32_t*>(&h);
}

// ---------------- Kernel 1: normalize centers -> bf16, zero out ----------------
__global__ void __launch_bounds__(256) prep_centers_kernel(const float* __restrict__ centers,
                                                           float* __restrict__ out) {
    __shared__ float wss[8];
    const int row = blockIdx.x;
    const int t = threadIdx.x;

    float4 v = reinterpret_cast<const float4*>(centers + (size_t)row * D_DIM)[t];
    float ss = v.x * v.x + v.y * v.y + v.z * v.z + v.w * v.w;
#pragma unroll
    for (int o = 16; o; o >>= 1) ss += __shfl_xor_sync(0xFFFFFFFFu, ss, o);
    if ((t & 31) == 0) wss[t >> 5] = ss;
    __syncthreads();
    if (t < 32) {
        float x = (t < 8) ? wss[t] : 0.f;
#pragma unroll
        for (int o = 4; o; o >>= 1) x += __shfl_xor_sync(0xFFFFFFFFu, x, o);
        if (t == 0) wss[0] = x;
    }
    __syncthreads();
    const float sc = 1.0f / fmaxf(sqrtf(wss[0]), EPS_F);

    __nv_bfloat162* orow = reinterpret_cast<__nv_bfloat162*>(g_cbf + (size_t)row * D_DIM);
    orow[t * 2]     = __floats2bfloat162_rn(v.x * sc, v.y * sc);
    orow[t * 2 + 1] = __floats2bfloat162_rn(v.z * sc, v.w * sc);

    if (row == 0 && t == 0) out[0] = 0.f;
}

// ---------------- Kernel 2: GEMM chunk (mma.sync bf16) + partial softmax ----------------
// grid = 1024: mtile = bid>>1 (128 rows), chunk = bid&1 (256 centers)
// 512 threads = 16 warps, warp grid 4(m) x 4(n), warp tile 64x64? -> wm covers 32 rows, wn 64 cols
// SMEM layout (1024-aligned base):
#define OFF_A     0u            // 2 x (128 x 128B) = 32768
#define OFF_B     32768u        // 2 x (256 x 128B) = 65536
#define OFF_SS    98304u        // 512 f
#define OFF_SCALE 100352u       // 128 f
#define OFF_MM    100864u       // 4*128 f
#define OFF_MS    102912u       // 4*128 f
#define OFF_MLV   104960u       // 4*128 f -> end 107008
#define SMEM_DYN  (107008 + 1024)

__global__ void __launch_bounds__(512, 1)
gemm_chunk_kernel(const float* __restrict__ emb,
                  const long long* __restrict__ labels) {
    extern __shared__ uint8_t dyn[];
    const uint32_t sb = smem_u32(dyn);
    const uint32_t base = (sb + 1023u) & ~1023u;
    uint8_t* gbase = dyn + (base - sb);

    float* ss_arr  = reinterpret_cast<float*>(gbase + OFF_SS);
    float* sc_arr  = reinterpret_cast<float*>(gbase + OFF_SCALE);
    float* sm_m    = reinterpret_cast<float*>(gbase + OFF_MM);
    float* sm_s    = reinterpret_cast<float*>(gbase + OFF_MS);
    float* sm_lv   = reinterpret_cast<float*>(gbase + OFF_MLV);

    const int t     = threadIdx.x;
    const int lane  = t & 31;
    const int wid   = t >> 5;
    const int wm    = wid & 3;    // 32-row slice
    const int wn    = wid >> 2;   // 64-col slice
    const int bid   = blockIdx.x;
    const int mtile = bid >> 1;
    const int chunk = bid & 1;
    const int row0  = mtile * TILE_M;

    // A loader mapping: row = t>>2 (0..127), quarter q = t&3 (16 floats each)
    const int arow = t >> 2, aq = t & 3;
    const float4* agp = reinterpret_cast<const float4*>(
        emb + (size_t)(row0 + arow) * D_DIM + aq * 16);
    const uint32_t a_sts0 = SWZ((uint32_t)(arow * 128 + aq * 32));
    const uint32_t a_sts1 = SWZ((uint32_t)(arow * 128 + aq * 32 + 16));

    float myss = 0.f;
    float4 av[4];

    auto ldA = [&](int kb) {
        const float4* p = agp + kb * 16;  // kb*64 floats = kb*16 float4
#pragma unroll
        for (int i = 0; i < 4; ++i) av[i] = p[i];
    };
    auto stA = [&](uint32_t Ab) {
#pragma unroll
        for (int i = 0; i < 4; ++i)
            myss += av[i].x * av[i].x + av[i].y * av[i].y +
                    av[i].z * av[i].z + av[i].w * av[i].w;
        asm volatile("st.shared.v4.b32 [%0], {%1,%2,%3,%4};"
                     :: "r"(Ab + a_sts0),
                        "r"(pk(av[0].x, av[0].y)), "r"(pk(av[0].z, av[0].w)),
                        "r"(pk(av[1].x, av[1].y)), "r"(pk(av[1].z, av[1].w)));
        asm volatile("st.shared.v4.b32 [%0], {%1,%2,%3,%4};"
                     :: "r"(Ab + a_sts1),
                        "r"(pk(av[2].x, av[2].y)), "r"(pk(av[2].z, av[2].w)),
                        "r"(pk(av[3].x, av[3].y)), "r"(pk(av[3].z, av[3].w)));
    };
    auto ldB = [&](int kb, uint32_t Bb) {
#pragma unroll
        for (int i = 0; i < 4; ++i) {
            int c = i * 512 + t;            // 2048 16B chunks
            int brow = c >> 3, off = c & 7;
            const void* src = g_cbf + (size_t)(chunk * CH_N + brow) * D_DIM + kb * 64 + off * 8;
            cp16(base + Bb + SWZ((uint32_t)(brow * 128 + off * 16)), src);
        }
        CP_COMMIT();
    };

    float c[2][8][4];
#pragma unroll
    for (int am = 0; am < 2; ++am)
#pragma unroll
        for (int an = 0; an < 8; ++an)
#pragma unroll
            for (int k = 0; k < 4; ++k) c[am][an][k] = 0.f;

    // ---- prologue: fill buffer 0 ----
    ldA(0);
    ldB(0, OFF_B);
    stA(base + OFF_A);
    CP_WAIT0();
    __syncthreads();

    const int rlow = lane & 15;
    const int bhi  = (lane >> 4) * 16;

#pragma unroll 1
    for (int kb = 0; kb < NSLABS; ++kb) {
        const int cur = kb & 1, nxt = cur ^ 1;
        const uint32_t Ab = base + OFF_A + cur * 16384u;
        const uint32_t Bb = base + OFF_B + cur * 32768u;

        if (kb + 1 < NSLABS) {
            ldA(kb + 1);
            ldB(kb + 1, OFF_B + nxt * 32768u);
        }

#pragma unroll
        for (int ks = 0; ks < 4; ++ks) {
            const uint32_t byt = (uint32_t)(ks * 32 + bhi);
            uint32_t af[2][4], bf[4][4];
#pragma unroll
            for (int am = 0; am < 2; ++am)
                ldsm4(af[am], Ab + SWZ((uint32_t)((wm * 32 + am * 16 + rlow) * 128) + byt));
#pragma unroll
            for (int p = 0; p < 4; ++p)
                ldsm4(bf[p], Bb + SWZ((uint32_t)((wn * 64 + p * 16 + rlow) * 128) + byt));
#pragma unroll
            for (int am = 0; am < 2; ++am)
#pragma unroll
                for (int p = 0; p < 4; ++p) {
                    mma16816(c[am][2 * p],     af[am], bf[p][0], bf[p][2]);
                    mma16816(c[am][2 * p + 1], af[am], bf[p][1], bf[p][3]);
                }
        }

        if (kb + 1 < NSLABS) {
            stA(base + OFF_A + nxt * 16384u);
            CP_WAIT0();
        }
        __syncthreads();
    }

    // ---- row scales ----
    ss_arr[t] = myss;
    __syncthreads();
    if (t < TILE_M) {
        float s2 = ss_arr[4 * t] + ss_arr[4 * t + 1] + ss_arr[4 * t + 2] + ss_arr[4 * t + 3];
        sc_arr[t] = 1.0f / (fmaxf(sqrtf(s2), EPS_F) * TAU_F);
    }
    __syncthreads();

    // ---- per-warp partial softmax over its 64 cols ----
    const int ql = lane >> 2, qc = lane & 3;
#pragma unroll
    for (int am = 0; am < 2; ++am) {
#pragma unroll
        for (int h = 0; h < 2; ++h) {
            const int r = wm * 32 + am * 16 + ql + 8 * h;
            const float sc = sc_arr[r];
            const int lc = (int)labels[row0 + r];

            float m = -1e30f;
            float v[16];
#pragma unroll
            for (int an = 0; an < 8; ++an)
#pragma unroll
                for (int e = 0; e < 2; ++e) {
                    float x = c[am][an][2 * h + e] * sc;
                    v[an * 2 + e] = x;
                    m = fmaxf(m, x);
                }
            m = fmaxf(m, __shfl_xor_sync(0xFFFFFFFFu, m, 1));
            m = fmaxf(m, __shfl_xor_sync(0xFFFFFFFFu, m, 2));

            float s = 0.f, lv = 0.f;
#pragma unroll
            for (int an = 0; an < 8; ++an)
#pragma unroll
                for (int e = 0; e < 2; ++e) {
                    s += __expf(v[an * 2 + e] - m);
                    const int col = chunk * CH_N + wn * 64 + an * 8 + qc * 2 + e;
                    if (col == lc) lv = v[an * 2 + e];
                }
            s  += __shfl_xor_sync(0xFFFFFFFFu, s, 1);
            s  += __shfl_xor_sync(0xFFFFFFFFu, s, 2);
            lv += __shfl_xor_sync(0xFFFFFFFFu, lv, 1);
            lv += __shfl_xor_sync(0xFFFFFFFFu, lv, 2);

            if (qc == 0) {
                sm_m[wn * 128 + r]  = m;
                sm_s[wn * 128 + r]  = s;
                sm_lv[wn * 128 + r] = lv;
            }
        }
    }
    __syncthreads();

    // ---- merge 4 warp-columns, write chunk partials ----
    if (t < TILE_M) {
        float M = -1e30f;
#pragma unroll
        for (int w = 0; w < 4; ++w) M = fmaxf(M, sm_m[w * 128 + t]);
        float S = 0.f, LV = 0.f;
#pragma unroll
        for (int w = 0; w < 4; ++w) {
            S  += sm_s[w * 128 + t] * __expf(sm_m[w * 128 + t] - M);
            LV += sm_lv[w * 128 + t];
        }
        const int gr = row0 + t;
        g_pm[chunk * N_ROWS + gr]  = M;
        g_ps[chunk * N_ROWS + gr]  = S;
        g_plv[chunk * N_ROWS + gr] = LV;
    }
}

// ---------------- Kernel 3: finalize ----------------
__global__ void __launch_bounds__(256) finalize_kernel(float* __restrict__ out) {
    __shared__ float wsum[8];
    const int r = blockIdx.x * 256 + threadIdx.x;

    const float m0 = g_pm[r],           m1 = g_pm[N_ROWS + r];
    const float s0 = g_ps[r],           s1 = g_ps[N_ROWS + r];
    const float lv = g_plv[r] + g_plv[N_ROWS + r];
    const float M  = fmaxf(m0, m1);
    const float S  = s0 * expf(m0 - M) + s1 * expf(m1 - M);
    float loss = (M + logf(S)) - lv;

#pragma unroll
    for (int o = 16; o; o >>= 1) loss += __shfl_xor_sync(0xFFFFFFFFu, loss, o);
    const int t = threadIdx.x;
    if ((t & 31) == 0) wsum[t >> 5] = loss;
    __syncthreads();
    if (t < 32) {
        float x = (t < 8) ? wsum[t] : 0.f;
#pragma unroll
        for (int o = 4; o; o >>= 1) x += __shfl_xor_sync(0xFFFFFFFFu, x, o);
        if (t == 0) atomicAdd(out, x * (1.0f / (float)N_ROWS));
    }
}

// ---------------- Launch ----------------
extern "C" void kernel_launch(void* const* d_in, const int* in_sizes, int n_in,
                              void* d_out, int out_size) {
    const float* emb       = (const float*)d_in[0];
    const float* centers   = (const float*)d_in[1];
    const long long* label = (const long long*)d_in[2];
    float* out             = (float*)d_out;

    cudaFuncSetAttribute(gemm_chunk_kernel, cudaFuncAttributeMaxDynamicSharedMemorySize, SMEM_DYN);

    prep_centers_kernel<<<K_CENT, 256>>>(centers, out);
    gemm_chunk_kernel<<<(N_ROWS / TILE_M) * NCHUNK, 512, SMEM_DYN>>>(emb, label);
    finalize_kernel<<<N_ROWS / 256, 256>>>(out);
}

// round 3
// speedup vs baseline: 1.0042x; 1.0042x over previous
#include <cuda_runtime.h>
#include <cuda_bf16.h>
#include <cstdint>

#define N_ROWS   65536
#define K_CENT   512
#define D_DIM    1024
#define TILE_M   128
#define CH_N     256          // centers per chunk
#define NCHUNK   2
#define KSLAB    64
#define NSLABS   (D_DIM / KSLAB)   // 16
#define TAU_F    0.1f
#define EPS_F    1e-8f

// Normalized centers in bf16 (1/||c|| folded in), row-major [K_CENT][D_DIM]
__device__ __align__(16) __nv_bfloat16 g_cbf[K_CENT * D_DIM];
// Normalized embeddings in bf16 with 1/(||e||*tau) folded in, [N_ROWS][D_DIM]
__device__ __align__(16) __nv_bfloat16 g_ebf[(size_t)N_ROWS * D_DIM];
// Per-chunk partial softmax stats
__device__ float g_pm[NCHUNK * N_ROWS];
__device__ float g_ps[NCHUNK * N_ROWS];
__device__ float g_plv[NCHUNK * N_ROWS];

// ---------------- helpers ----------------
__device__ __forceinline__ uint32_t smem_u32(const void* p) {
    uint32_t a;
    asm("{ .reg .u64 t; cvta.to.shared.u64 t, %1; cvt.u32.u64 %0, t; }" : "=r"(a) : "l"(p));
    return a;
}
#define SWZ(o) ((o) ^ ((((uint32_t)(o)) >> 3) & 0x70u))

__device__ __forceinline__ void cp16(uint32_t dst, const void* src) {
    asm volatile("cp.async.cg.shared.global [%0], [%1], 16;"
                 :: "r"(dst), "l"(__cvta_generic_to_global(src)) : "memory");
}
#define CP_COMMIT() asm volatile("cp.async.commit_group;" ::: "memory")
#define CP_WAIT1()  asm volatile("cp.async.wait_group 1;" ::: "memory")

__device__ __forceinline__ void ldsm4(uint32_t* r, uint32_t addr) {
    asm volatile("ldmatrix.sync.aligned.m8n8.x4.shared.b16 {%0,%1,%2,%3}, [%4];"
                 : "=r"(r[0]), "=r"(r[1]), "=r"(r[2]), "=r"(r[3]) : "r"(addr));
}

__device__ __forceinline__ void mma16816(float* d, const uint32_t* a,
                                         uint32_t b0, uint32_t b1) {
    asm volatile(
        "mma.sync.aligned.m16n8k16.row.col.f32.bf16.bf16.f32 "
        "{%0,%1,%2,%3}, {%4,%5,%6,%7}, {%8,%9}, {%0,%1,%2,%3};"
        : "+f"(d[0]), "+f"(d[1]), "+f"(d[2]), "+f"(d[3])
        : "r"(a[0]), "r"(a[1]), "r"(a[2]), "r"(a[3]), "r"(b0), "r"(b1));
}

__device__ __forceinline__ uint32_t pk(float x, float y) {
    __nv_bfloat162 h = __floats2bfloat162_rn(x, y);
    return *reinterpret_cast<uint32_t*>(&h);
}

// ---------------- Kernel 1: normalize centers -> bf16, zero out ----------------
__global__ void __launch_bounds__(256) prep_centers_kernel(const float* __restrict__ centers,
                                                           float* __restrict__ out) {
    __shared__ float wss[8];
    const int row = blockIdx.x;
    const int t = threadIdx.x;

    float4 v = reinterpret_cast<const float4*>(centers + (size_t)row * D_DIM)[t];
    float ss = v.x * v.x + v.y * v.y + v.z * v.z + v.w * v.w;
#pragma unroll
    for (int o = 16; o; o >>= 1) ss += __shfl_xor_sync(0xFFFFFFFFu, ss, o);
    if ((t & 31) == 0) wss[t >> 5] = ss;
    __syncthreads();
    if (t < 32) {
        float x = (t < 8) ? wss[t] : 0.f;
#pragma unroll
        for (int o = 4; o; o >>= 1) x += __shfl_xor_sync(0xFFFFFFFFu, x, o);
        if (t == 0) wss[0] = x;
    }
    __syncthreads();
    const float sc = 1.0f / fmaxf(sqrtf(wss[0]), EPS_F);

    __nv_bfloat162* orow = reinterpret_cast<__nv_bfloat162*>(g_cbf + (size_t)row * D_DIM);
    orow[t * 2]     = __floats2bfloat162_rn(v.x * sc, v.y * sc);
    orow[t * 2 + 1] = __floats2bfloat162_rn(v.z * sc, v.w * sc);

    if (row == 0 && t == 0) out[0] = 0.f;
}

// ---------------- Kernel 1b: embeddings -> bf16 with 1/(||e||*tau) folded ----------------
// warp per row; 8 warps/block; grid = N_ROWS/8
__global__ void __launch_bounds__(256) prep_emb_kernel(const float* __restrict__ emb) {
    const int lane = threadIdx.x & 31;
    const int wrp  = threadIdx.x >> 5;
    const int row  = blockIdx.x * 8 + wrp;

    const float4* src = reinterpret_cast<const float4*>(emb + (size_t)row * D_DIM);
    float4 v[8];
    float ss = 0.f;
#pragma unroll
    for (int j = 0; j < 8; ++j) {
        v[j] = src[lane + j * 32];
        ss += v[j].x * v[j].x + v[j].y * v[j].y + v[j].z * v[j].z + v[j].w * v[j].w;
    }
#pragma unroll
    for (int o = 16; o; o >>= 1) ss += __shfl_xor_sync(0xFFFFFFFFu, ss, o);
    const float sc = 1.0f / (fmaxf(sqrtf(ss), EPS_F) * TAU_F);

    uint2* dst = reinterpret_cast<uint2*>(g_ebf + (size_t)row * D_DIM);
#pragma unroll
    for (int j = 0; j < 8; ++j) {
        uint2 o;
        o.x = pk(v[j].x * sc, v[j].y * sc);
        o.y = pk(v[j].z * sc, v[j].w * sc);
        dst[lane + j * 32] = o;
    }
}

// ---------------- Kernel 2: GEMM chunk (mma.sync bf16) + partial softmax ----------------
// grid = 1024: mtile = bid>>1 (128 rows), chunk = bid&1 (256 centers)
// 512 threads = 16 warps, warp grid 4(m) x 4(n): warp tile 32 rows x 64 cols
// SMEM (1024-aligned base), 3-stage pipeline:
#define A_STG     16384u
#define B_STG     32768u
#define OFF_A     0u              // 3 x 16384 = 49152
#define OFF_B     49152u          // 3 x 32768 = 98304 -> end 147456
#define OFF_MM    147456u         // 4*128 f = 2048
#define OFF_MS    149504u
#define OFF_MLV   151552u         // end 153600
#define SMEM_DYN  (153600 + 1024)

__global__ void __launch_bounds__(512, 1)
gemm_chunk_kernel(const long long* __restrict__ labels) {
    extern __shared__ uint8_t dyn[];
    const uint32_t sb = smem_u32(dyn);
    const uint32_t base = (sb + 1023u) & ~1023u;
    uint8_t* gbase = dyn + (base - sb);

    float* sm_m  = reinterpret_cast<float*>(gbase + OFF_MM);
    float* sm_s  = reinterpret_cast<float*>(gbase + OFF_MS);
    float* sm_lv = reinterpret_cast<float*>(gbase + OFF_MLV);

    const int t     = threadIdx.x;
    const int lane  = t & 31;
    const int wid   = t >> 5;
    const int wm    = wid & 3;    // 32-row slice
    const int wn    = wid >> 2;   // 64-col slice
    const int bid   = blockIdx.x;
    const int mtile = bid >> 1;
    const int chunk = bid & 1;
    const int row0  = mtile * TILE_M;

    // loader mappings (16B chunks): c -> row = c>>3, off8 = c&7
    const int ar = t >> 3, ao = t & 7;   // A: 1024 chunks, 2 per thread (stride 512 -> +64 rows)
    const uint32_t a_sw0 = SWZ((uint32_t)(ar * 128 + ao * 16));
    const uint32_t a_sw1 = SWZ((uint32_t)((ar + 64) * 128 + ao * 16));
    const __nv_bfloat16* agp = g_ebf + (size_t)(row0 + ar) * D_DIM + ao * 8;
    const __nv_bfloat16* bgp = g_cbf + (size_t)(chunk * CH_N + ar) * D_DIM + ao * 8;

    auto issueA = [&](int kb, int stg) {
        const uint32_t Ad = base + OFF_A + (uint32_t)stg * A_STG;
        const __nv_bfloat16* s = agp + kb * KSLAB;
        cp16(Ad + a_sw0, s);
        cp16(Ad + a_sw1, s + (size_t)64 * D_DIM);
    };
    auto issueB = [&](int kb, int stg) {
        const uint32_t Bd = base + OFF_B + (uint32_t)stg * B_STG;
        const __nv_bfloat16* s = bgp + kb * KSLAB;
#pragma unroll
        for (int i = 0; i < 4; ++i) {
            cp16(Bd + SWZ((uint32_t)((ar + i * 64) * 128 + ao * 16)),
                 s + (size_t)(i * 64) * D_DIM);
        }
    };

    float c[2][8][4];
#pragma unroll
    for (int am = 0; am < 2; ++am)
#pragma unroll
        for (int an = 0; an < 8; ++an)
#pragma unroll
            for (int k = 0; k < 4; ++k) c[am][an][k] = 0.f;

    // ---- prologue: stages 0 and 1 in flight ----
    issueA(0, 0); issueB(0, 0); CP_COMMIT();
    issueA(1, 1); issueB(1, 1); CP_COMMIT();

    const int rlow = lane & 15;
    const int bhi  = (lane >> 4) * 16;

#pragma unroll 1
    for (int kb = 0; kb < NSLABS; ++kb) {
        const int stg = kb % 3;
        const uint32_t Ab = base + OFF_A + (uint32_t)stg * A_STG;
        const uint32_t Bb = base + OFF_B + (uint32_t)stg * B_STG;

        CP_WAIT1();              // slab kb resident
        __syncthreads();

        if (kb + 2 < NSLABS) {
            const int ns = (kb + 2) % 3;
            issueA(kb + 2, ns);
            issueB(kb + 2, ns);
        }
        CP_COMMIT();             // one group per iteration keeps wait_group 1 aligned

#pragma unroll
        for (int ks = 0; ks < 4; ++ks) {
            const uint32_t byt = (uint32_t)(ks * 32 + bhi);
            uint32_t af[2][4], bf[4][4];
#pragma unroll
            for (int am = 0; am < 2; ++am)
                ldsm4(af[am], Ab + SWZ((uint32_t)((wm * 32 + am * 16 + rlow) * 128) + byt));
#pragma unroll
            for (int p = 0; p < 4; ++p)
                ldsm4(bf[p], Bb + SWZ((uint32_t)((wn * 64 + p * 16 + rlow) * 128) + byt));
#pragma unroll
            for (int am = 0; am < 2; ++am)
#pragma unroll
                for (int p = 0; p < 4; ++p) {
                    mma16816(c[am][2 * p],     af[am], bf[p][0], bf[p][2]);
                    mma16816(c[am][2 * p + 1], af[am], bf[p][1], bf[p][3]);
                }
        }
        __syncthreads();
    }

    // ---- per-warp partial softmax over its 64 cols (scale pre-folded) ----
    const int ql = lane >> 2, qc = lane & 3;
#pragma unroll
    for (int am = 0; am < 2; ++am) {
#pragma unroll
        for (int h = 0; h < 2; ++h) {
            const int r = wm * 32 + am * 16 + ql + 8 * h;
            const int lc = (int)labels[row0 + r];

            float m = -1e30f;
            float v[16];
#pragma unroll
            for (int an = 0; an < 8; ++an)
#pragma unroll
                for (int e = 0; e < 2; ++e) {
                    float x = c[am][an][2 * h + e];
                    v[an * 2 + e] = x;
                    m = fmaxf(m, x);
                }
            m = fmaxf(m, __shfl_xor_sync(0xFFFFFFFFu, m, 1));
            m = fmaxf(m, __shfl_xor_sync(0xFFFFFFFFu, m, 2));

            float s = 0.f, lv = 0.f;
#pragma unroll
            for (int an = 0; an < 8; ++an)
#pragma unroll
                for (int e = 0; e < 2; ++e) {
                    s += __expf(v[an * 2 + e] - m);
                    const int col = chunk * CH_N + wn * 64 + an * 8 + qc * 2 + e;
                    if (col == lc) lv = v[an * 2 + e];
                }
            s  += __shfl_xor_sync(0xFFFFFFFFu, s, 1);
            s  += __shfl_xor_sync(0xFFFFFFFFu, s, 2);
            lv += __shfl_xor_sync(0xFFFFFFFFu, lv, 1);
            lv += __shfl_xor_sync(0xFFFFFFFFu, lv, 2);

            if (qc == 0) {
                sm_m[wn * 128 + r]  = m;
                sm_s[wn * 128 + r]  = s;
                sm_lv[wn * 128 + r] = lv;
            }
        }
    }
    __syncthreads();

    // ---- merge 4 warp-columns, write chunk partials ----
    if (t < TILE_M) {
        float M = -1e30f;
#pragma unroll
        for (int w = 0; w < 4; ++w) M = fmaxf(M, sm_m[w * 128 + t]);
        float S = 0.f, LV = 0.f;
#pragma unroll
        for (int w = 0; w < 4; ++w) {
            S  += sm_s[w * 128 + t] * __expf(sm_m[w * 128 + t] - M);
            LV += sm_lv[w * 128 + t];
        }
        const int gr = row0 + t;
        g_pm[chunk * N_ROWS + gr]  = M;
        g_ps[chunk * N_ROWS + gr]  = S;
        g_plv[chunk * N_ROWS + gr] = LV;
    }
}

// ---------------- Kernel 3: finalize ----------------
__global__ void __launch_bounds__(256) finalize_kernel(float* __restrict__ out) {
    __shared__ float wsum[8];
    const int r = blockIdx.x * 256 + threadIdx.x;

    const float m0 = g_pm[r],           m1 = g_pm[N_ROWS + r];
    const float s0 = g_ps[r],           s1 = g_ps[N_ROWS + r];
    const float lv = g_plv[r] + g_plv[N_ROWS + r];
    const float M  = fmaxf(m0, m1);
    const float S  = s0 * expf(m0 - M) + s1 * expf(m1 - M);
    float loss = (M + logf(S)) - lv;

#pragma unroll
    for (int o = 16; o; o >>= 1) loss += __shfl_xor_sync(0xFFFFFFFFu, loss, o);
    const int t = threadIdx.x;
    if ((t & 31) == 0) wsum[t >> 5] = loss;
    __syncthreads();
    if (t < 32) {
        float x = (t < 8) ? wsum[t] : 0.f;
#pragma unroll
        for (int o = 4; o; o >>= 1) x += __shfl_xor_sync(0xFFFFFFFFu, x, o);
        if (t == 0) atomicAdd(out, x * (1.0f / (float)N_ROWS));
    }
}

// ---------------- Launch ----------------
extern "C" void kernel_launch(void* const* d_in, const int* in_sizes, int n_in,
                              void* d_out, int out_size) {
    const float* emb       = (const float*)d_in[0];
    const float* centers   = (const float*)d_in[1];
    const long long* label = (const long long*)d_in[2];
    float* out             = (float*)d_out;

    cudaFuncSetAttribute(gemm_chunk_kernel, cudaFuncAttributeMaxDynamicSharedMemorySize, SMEM_DYN);

    prep_centers_kernel<<<K_CENT, 256>>>(centers, out);
    prep_emb_kernel<<<N_ROWS / 8, 256>>>(emb);
    gemm_chunk_kernel<<<(N_ROWS / TILE_M) * NCHUNK, 512, SMEM_DYN>>>(label);
    finalize_kernel<<<N_ROWS / 256, 256>>>(out);
}